// round 16
// baseline (speedup 1.0000x reference)
#include <cuda_runtime.h>
#include <cuda_fp16.h>
#include <cstdint>
#include <cstddef>

// ---------------- problem constants ----------------
#define Bq    4
#define NTOK  4096
#define CDIM  768
#define Hh    8
#define HDd   96
#define MROWS (Bq * NTOK)          // 16384
#define SPLIT 16
#define BHn   (Bq * Hh)            // 32
#define MT    (MROWS / 128)        // 128 m-tiles
#define SCALE_F 0.10206207261596577f
#define EPSN 1e-12f

// ---------------- scratch (device globals) ----------------
__device__ __half g_a1f[(size_t)MROWS * CDIM];       // fp16 context_x
__device__ __half g_a2f[(size_t)MROWS * CDIM];       // fp16 depth_x
__device__ __half g_qh [(size_t)MROWS * CDIM];       // fp16 q
__device__ __half g_kvh[(size_t)MROWS * 2 * CDIM];   // fp16 kv
__device__ __half g_wqf[CDIM * CDIM];
__device__ __half g_wkf[2 * CDIM * CDIM];
__device__ __half g_wpf[CDIM * CDIM];
__device__ __half g_attnh[BHn * HDd * HDd];          // fp16 softmaxed attn
__device__ __half g_mt  [Bq * CDIM * CDIM];          // per-batch folded weights M^T
__device__ __half g_parth[(size_t)SPLIT * BHn * HDd * HDd];  // fp16 Gram partials
__device__ float g_qsqp[MT * CDIM];                  // per-mtile col sumsq (q)
__device__ float g_ksqp[MT * CDIM];                  // per-mtile col sumsq (k)
__device__ float g_inq [BHn * HDd];
__device__ float g_ink [BHn * HDd];

// ---------------- helpers ----------------
__device__ __forceinline__ uint32_t s2u(const void* p) {
    uint32_t a;
    asm("{ .reg .u64 t; cvta.to.shared.u64 t, %1; cvt.u32.u64 %0, t; }" : "=r"(a) : "l"(p));
    return a;
}
__device__ __forceinline__ void cp16(uint32_t dst, const void* src) {
    asm volatile("cp.async.cg.shared.global [%0], [%1], 16;" :: "r"(dst), "l"(src));
}
__device__ __forceinline__ void cp_commit() { asm volatile("cp.async.commit_group;"); }
template <int N>
__device__ __forceinline__ void cp_wait() { asm volatile("cp.async.wait_group %0;" :: "n"(N)); }

__device__ __forceinline__ void ldsm4(uint32_t& r0, uint32_t& r1, uint32_t& r2, uint32_t& r3,
                                      uint32_t addr) {
    asm volatile("ldmatrix.sync.aligned.m8n8.x4.shared.b16 {%0,%1,%2,%3}, [%4];"
                 : "=r"(r0), "=r"(r1), "=r"(r2), "=r"(r3) : "r"(addr));
}
__device__ __forceinline__ void ldsm4t(uint32_t& r0, uint32_t& r1, uint32_t& r2, uint32_t& r3,
                                       uint32_t addr) {
    asm volatile("ldmatrix.sync.aligned.m8n8.x4.trans.shared.b16 {%0,%1,%2,%3}, [%4];"
                 : "=r"(r0), "=r"(r1), "=r"(r2), "=r"(r3) : "r"(addr));
}
__device__ __forceinline__ void mma_f16(float& c0, float& c1, float& c2, float& c3,
                                        uint32_t a0, uint32_t a1, uint32_t a2, uint32_t a3,
                                        uint32_t b0, uint32_t b1) {
    asm volatile(
        "mma.sync.aligned.m16n8k16.row.col.f32.f16.f16.f32 "
        "{%0,%1,%2,%3}, {%4,%5,%6,%7}, {%8,%9}, {%0,%1,%2,%3};"
        : "+f"(c0), "+f"(c1), "+f"(c2), "+f"(c3)
        : "r"(a0), "r"(a1), "r"(a2), "r"(a3), "r"(b0), "r"(b1));
}

// ============================================================
// GEMM core config
// ============================================================
#define PIPE      3
#define TILE_B    16384
#define STAGE_B   (2 * TILE_B)
#define GSMEM     (PIPE * STAGE_B)     // 98304
#define NKT       12
#define NT1       6

// ============================================================
// Fused projection GEMM + column sumsq partials
// ============================================================
__global__ __launch_bounds__(256, 2) void gemm_proj(
    const __half* __restrict__ A1, const __half* __restrict__ B1, __half* __restrict__ O1,
    const __half* __restrict__ A2, const __half* __restrict__ B2, __half* __restrict__ O2)
{
    extern __shared__ __align__(1024) char smem[];
    const uint32_t sbase = s2u(smem);

    const bool j2 = blockIdx.x >= NT1;
    const __half* __restrict__ A = j2 ? A2 : A1;
    const __half* __restrict__ B = j2 ? B2 : B1;
    __half* __restrict__ O = j2 ? O2 : O1;
    const int Nc = j2 ? 2 * CDIM : CDIM;
    const int n0 = (j2 ? (int)blockIdx.x - NT1 : (int)blockIdx.x) * 128;
    const int m0 = blockIdx.y * 128;

    const int tid  = threadIdx.x;
    const int lane = tid & 31;
    const int wid  = tid >> 5;
    const int wm = (wid >> 2) * 64;
    const int wn = (wid & 3) * 32;

    const uint32_t a_row   = wm + (lane & 15);
    const uint32_t a_swz   = (lane & 7) * 16;
    const uint32_t a_xhalf = (lane >> 4) * 16;
    const int l8 = lane & 7;
    const int lg = lane >> 3;
    const uint32_t b_row_base = wn + (lg >> 1) * 8 + l8;
    const uint32_t b_khalf    = (lg & 1) * 16;
    const uint32_t b_swz      = l8 * 16;

    float acc[4][4][4];
    #pragma unroll
    for (int i = 0; i < 4; i++)
        #pragma unroll
        for (int j = 0; j < 4; j++)
            #pragma unroll
            for (int c = 0; c < 4; c++) acc[i][j][c] = 0.f;

    auto issue = [&](int kt, int slot) {
        const int k0 = kt * 64;
        const uint32_t sA = sbase + slot * STAGE_B;
        const uint32_t sB = sA + TILE_B;
        #pragma unroll
        for (int i = 0; i < 8; i++) {
            const int c = tid + i * 256;
            const int row = (c >> 3) & 127;
            const int x16 = c & 7;
            const uint32_t off = (uint32_t)(row * 128 + ((x16 * 16) ^ ((row & 7) * 16)));
            if (c < 1024) cp16(sA + off, A + (size_t)(m0 + row) * CDIM + k0 + x16 * 8);
            else          cp16(sB + off, B + (size_t)(n0 + row) * CDIM + k0 + x16 * 8);
        }
        cp_commit();
    };

    issue(0, 0); issue(1, 1);

    for (int kt = 0; kt < NKT; kt++) {
        const int slot = kt % 3;
        cp_wait<PIPE - 2>();
        __syncthreads();
        if (kt + 2 < NKT) issue(kt + 2, (kt + 2) % 3);

        const uint32_t sA = sbase + slot * STAGE_B;
        const uint32_t sB = sA + TILE_B;

        #pragma unroll
        for (int ks = 0; ks < 4; ks++) {
            uint32_t af[4][4];
            #pragma unroll
            for (int mi = 0; mi < 4; mi++) {
                const uint32_t addr = sA + (a_row + mi * 16) * 128
                                    + ((ks * 32 + a_xhalf) ^ a_swz);
                ldsm4(af[mi][0], af[mi][1], af[mi][2], af[mi][3], addr);
            }
            uint32_t bf[4][2];
            #pragma unroll
            for (int p = 0; p < 2; p++) {
                const uint32_t addr = sB + (b_row_base + p * 16) * 128
                                    + ((ks * 32 + b_khalf) ^ b_swz);
                ldsm4(bf[2*p][0], bf[2*p][1], bf[2*p+1][0], bf[2*p+1][1], addr);
            }
            #pragma unroll
            for (int mi = 0; mi < 4; mi++)
                #pragma unroll
                for (int nj = 0; nj < 4; nj++)
                    mma_f16(acc[mi][nj][0], acc[mi][nj][1], acc[mi][nj][2], acc[mi][nj][3],
                            af[mi][0], af[mi][1], af[mi][2], af[mi][3],
                            bf[nj][0], bf[nj][1]);
        }
    }

    #pragma unroll
    for (int mi = 0; mi < 4; mi++) {
        const int r0 = m0 + wm + mi * 16 + (lane >> 2);
        #pragma unroll
        for (int nj = 0; nj < 4; nj++) {
            const int c = n0 + wn + nj * 8 + (lane & 3) * 2;
            __half2 v0 = { __float2half_rn(acc[mi][nj][0]), __float2half_rn(acc[mi][nj][1]) };
            __half2 v1 = { __float2half_rn(acc[mi][nj][2]), __float2half_rn(acc[mi][nj][3]) };
            *reinterpret_cast<__half2*>(O + (size_t)r0 * Nc + c) = v0;
            *reinterpret_cast<__half2*>(O + (size_t)(r0 + 8) * Nc + c) = v1;
        }
    }

    // ---- fused column sum-of-squares ----
    const bool need_sq = (!j2) || (n0 < CDIM);
    if (need_sq) {
        float* colsq = reinterpret_cast<float*>(smem);   // [2][128]
        __syncthreads();
        #pragma unroll
        for (int nj = 0; nj < 4; nj++) {
            float s0 = 0.f, s1 = 0.f;
            #pragma unroll
            for (int mi = 0; mi < 4; mi++) {
                s0 += acc[mi][nj][0] * acc[mi][nj][0] + acc[mi][nj][2] * acc[mi][nj][2];
                s1 += acc[mi][nj][1] * acc[mi][nj][1] + acc[mi][nj][3] * acc[mi][nj][3];
            }
            #pragma unroll
            for (int o = 4; o < 32; o <<= 1) {
                s0 += __shfl_xor_sync(0xffffffffu, s0, o);
                s1 += __shfl_xor_sync(0xffffffffu, s1, o);
            }
            if (lane < 4) {
                const int col = wn + nj * 8 + lane * 2;
                colsq[(wm >> 6) * 128 + col]     = s0;
                colsq[(wm >> 6) * 128 + col + 1] = s1;
            }
        }
        __syncthreads();
        if (tid < 128) {
            const float tot = colsq[tid] + colsq[128 + tid];
            float* dst = j2 ? g_ksqp : g_qsqp;
            dst[(size_t)blockIdx.y * CDIM + n0 + tid] = tot;
        }
    }
}

// ============================================================
// Final GEMM: out = V @ M_b + bias, fp32 output
// ============================================================
__global__ __launch_bounds__(256, 2) void gemm_out(
    const float* __restrict__ bias, float* __restrict__ Cout)
{
    extern __shared__ __align__(1024) char smem[];
    const uint32_t sbase = s2u(smem);
    const int Nc = CDIM;

    const int tid  = threadIdx.x;
    const int lane = tid & 31;
    const int wid  = tid >> 5;
    const int m0 = blockIdx.y * 128;
    const int n0 = blockIdx.x * 128;
    const int wm = (wid >> 2) * 64;
    const int wn = (wid & 3) * 32;

    const __half* __restrict__ A = g_kvh + CDIM;          // v half, row stride 2C
    const __half* __restrict__ B = g_mt + (size_t)(blockIdx.y >> 5) * CDIM * CDIM;

    const uint32_t a_row   = wm + (lane & 15);
    const uint32_t a_swz   = (lane & 7) * 16;
    const uint32_t a_xhalf = (lane >> 4) * 16;
    const int l8 = lane & 7;
    const int lg = lane >> 3;
    const uint32_t b_row_base = wn + (lg >> 1) * 8 + l8;
    const uint32_t b_khalf    = (lg & 1) * 16;
    const uint32_t b_swz      = l8 * 16;

    float acc[4][4][4];
    #pragma unroll
    for (int i = 0; i < 4; i++)
        #pragma unroll
        for (int j = 0; j < 4; j++)
            #pragma unroll
            for (int c = 0; c < 4; c++) acc[i][j][c] = 0.f;

    auto issue = [&](int kt, int slot) {
        const int k0 = kt * 64;
        const uint32_t sA = sbase + slot * STAGE_B;
        const uint32_t sB = sA + TILE_B;
        #pragma unroll
        for (int i = 0; i < 8; i++) {
            const int c = tid + i * 256;
            const int row = (c >> 3) & 127;
            const int x16 = c & 7;
            const uint32_t off = (uint32_t)(row * 128 + ((x16 * 16) ^ ((row & 7) * 16)));
            if (c < 1024) cp16(sA + off, A + (size_t)(m0 + row) * (2 * CDIM) + k0 + x16 * 8);
            else          cp16(sB + off, B + (size_t)(n0 + row) * CDIM + k0 + x16 * 8);
        }
        cp_commit();
    };

    issue(0, 0); issue(1, 1);

    for (int kt = 0; kt < NKT; kt++) {
        const int slot = kt % 3;
        cp_wait<PIPE - 2>();
        __syncthreads();
        if (kt + 2 < NKT) issue(kt + 2, (kt + 2) % 3);

        const uint32_t sA = sbase + slot * STAGE_B;
        const uint32_t sB = sA + TILE_B;

        #pragma unroll
        for (int ks = 0; ks < 4; ks++) {
            uint32_t af[4][4];
            #pragma unroll
            for (int mi = 0; mi < 4; mi++) {
                const uint32_t addr = sA + (a_row + mi * 16) * 128
                                    + ((ks * 32 + a_xhalf) ^ a_swz);
                ldsm4(af[mi][0], af[mi][1], af[mi][2], af[mi][3], addr);
            }
            uint32_t bf[4][2];
            #pragma unroll
            for (int p = 0; p < 2; p++) {
                const uint32_t addr = sB + (b_row_base + p * 16) * 128
                                    + ((ks * 32 + b_khalf) ^ b_swz);
                ldsm4(bf[2*p][0], bf[2*p][1], bf[2*p+1][0], bf[2*p+1][1], addr);
            }
            #pragma unroll
            for (int mi = 0; mi < 4; mi++)
                #pragma unroll
                for (int nj = 0; nj < 4; nj++)
                    mma_f16(acc[mi][nj][0], acc[mi][nj][1], acc[mi][nj][2], acc[mi][nj][3],
                            af[mi][0], af[mi][1], af[mi][2], af[mi][3],
                            bf[nj][0], bf[nj][1]);
        }
    }

    #pragma unroll
    for (int mi = 0; mi < 4; mi++) {
        const int r0 = m0 + wm + mi * 16 + (lane >> 2);
        #pragma unroll
        for (int nj = 0; nj < 4; nj++) {
            const int c = n0 + wn + nj * 8 + (lane & 3) * 2;
            const float b0 = bias[c], b1 = bias[c + 1];
            float2 v0 = { acc[mi][nj][0] + b0, acc[mi][nj][1] + b1 };
            float2 v1 = { acc[mi][nj][2] + b0, acc[mi][nj][3] + b1 };
            *reinterpret_cast<float2*>(Cout + (size_t)r0 * Nc + c) = v0;
            *reinterpret_cast<float2*>(Cout + (size_t)(r0 + 8) * Nc + c) = v1;
        }
    }
}

// ============================================================
// Fused prep: fp32->fp16 converts + weight transposes
// ============================================================
#define NBC 12288

__global__ __launch_bounds__(256) void prep_all(
    const float* __restrict__ cx, __half* __restrict__ a1f,
    const float* __restrict__ dx, __half* __restrict__ a2f,
    const float* __restrict__ Wq, const float* __restrict__ Wkv,
    const float* __restrict__ Wp,
    __half* __restrict__ Tq, __half* __restrict__ Tk, __half* __restrict__ Tp)
{
    const int bx = blockIdx.x;
    if (bx < 2 * NBC) {
        const bool sec = bx >= NBC;
        const float* in = sec ? dx : cx;
        __half* out = sec ? a2f : a1f;
        const int i = (sec ? bx - NBC : bx) * 256 + threadIdx.x;
        const float4 v = reinterpret_cast<const float4*>(in)[i];
        __half2 h0 = { __float2half_rn(v.x), __float2half_rn(v.y) };
        __half2 h1 = { __float2half_rn(v.z), __float2half_rn(v.w) };
        reinterpret_cast<__half2*>(out)[i * 2 + 0] = h0;
        reinterpret_cast<__half2*>(out)[i * 2 + 1] = h1;
        return;
    }
    __shared__ float t[32][33];
    const int w = bx - 2 * NBC;
    const int bnx = w % 96;
    const int k0 = (w / 96) * 32;
    const float* W; __half* T; int Nc, nt0;
    if (bnx < 24)      { W = Wq;  T = Tq; Nc = CDIM;     nt0 = 0; }
    else if (bnx < 72) { W = Wkv; T = Tk; Nc = 2 * CDIM; nt0 = 24; }
    else               { W = Wp;  T = Tp; Nc = CDIM;     nt0 = 72; }
    const int n0 = (bnx - nt0) * 32;
    const int tx = threadIdx.x & 31, ty = threadIdx.x >> 5;
    #pragma unroll
    for (int i = 0; i < 32; i += 8)
        t[ty + i][tx] = W[(size_t)(k0 + ty + i) * Nc + n0 + tx];
    __syncthreads();
    #pragma unroll
    for (int i = 0; i < 32; i += 8)
        T[(size_t)(n0 + ty + i) * CDIM + k0 + tx] = __float2half_rn(t[tx][ty + i]);
}

// ============================================================
// Reduce per-mtile partials -> reciprocal norms
// ============================================================
__global__ __launch_bounds__(96) void norm_reduce()
{
    const int bh = blockIdx.x;
    const int b  = bh >> 3;
    const int h  = bh & 7;
    const int d  = threadIdx.x;
    const int col = h * HDd + d;
    float sq = 0.f, sk = 0.f;
    #pragma unroll 8
    for (int j = 0; j < 32; j++) {
        sq += g_qsqp[(size_t)(b * 32 + j) * CDIM + col];
        sk += g_ksqp[(size_t)(b * 32 + j) * CDIM + col];
    }
    g_inq[bh * HDd + d] = 1.f / fmaxf(sqrtf(sq), EPSN);
    g_ink[bh * HDd + d] = 1.f / fmaxf(sqrtf(sk), EPSN);
}

// ============================================================
// Tensor-core Gram partials (fp16 output): 32-token stages, 3-stage pipe
// grid (BHn, SPLIT=16); 256 tokens per block; GNI=8
// ============================================================
#define GPITCH 104
#define GNI    8
#define GSTG   3

__global__ __launch_bounds__(192) void gram_tc()
{
    __shared__ __half qs[GSTG][32][GPITCH];
    __shared__ __half ks[GSTG][32][GPITCH];

    const int bh = blockIdx.x;
    const int b  = bh >> 3;
    const int h  = bh & 7;
    const int sp = blockIdx.y;
    const int nbase = b * NTOK + sp * (NTOK / SPLIT);

    const int tid  = threadIdx.x;
    const int lane = tid & 31;
    const int w    = tid >> 5;
    const int e0   = w * 16;

    const __half* qbase = g_qh  + (size_t)nbase * CDIM + h * HDd;
    const __half* kbase = g_kvh + (size_t)nbase * (2 * CDIM) + h * HDd;

    auto issue = [&](int it, int s) {
        const int n0 = it * 32;
        #pragma unroll
        for (int r = 0; r < 2; r++) {
            const int c = tid + r * 192;
            const int lrow = c / 12;
            const int lx   = c % 12;
            cp16(s2u(&qs[s][lrow][lx * 8]),
                 qbase + (size_t)(n0 + lrow) * CDIM + lx * 8);
            cp16(s2u(&ks[s][lrow][lx * 8]),
                 kbase + (size_t)(n0 + lrow) * (2 * CDIM) + lx * 8);
        }
        cp_commit();
    };

    const uint32_t a_row = (lane & 7) + ((lane >> 4) & 1) * 8;
    const uint32_t a_coff = ((lane >> 3) & 1) * 8;
    const uint32_t b_row = (lane & 7) + ((lane >> 3) & 1) * 8;
    const uint32_t b_coff = ((lane >> 4) & 1) * 8;

    float acc[6][2][4];
    #pragma unroll
    for (int i = 0; i < 6; i++)
        #pragma unroll
        for (int j = 0; j < 2; j++)
            #pragma unroll
            for (int c = 0; c < 4; c++) acc[i][j][c] = 0.f;

    issue(0, 0); issue(1, 1);

    #pragma unroll 1
    for (int it = 0; it < GNI; it++) {
        const int s = it % GSTG;
        if (it + 1 < GNI) cp_wait<1>(); else cp_wait<0>();
        __syncthreads();
        if (it + 2 < GNI) issue(it + 2, (it + 2) % GSTG);

        #pragma unroll
        for (int hs = 0; hs < 2; hs++) {
            uint32_t bf[4];
            ldsm4t(bf[0], bf[1], bf[2], bf[3],
                   s2u(&ks[s][hs * 16 + b_row][e0 + b_coff]));
            uint32_t af[6][4];
            #pragma unroll
            for (int mi = 0; mi < 6; mi++)
                ldsm4t(af[mi][0], af[mi][1], af[mi][2], af[mi][3],
                       s2u(&qs[s][hs * 16 + a_row][mi * 16 + a_coff]));
            #pragma unroll
            for (int mi = 0; mi < 6; mi++)
                #pragma unroll
                for (int nj = 0; nj < 2; nj++)
                    mma_f16(acc[mi][nj][0], acc[mi][nj][1], acc[mi][nj][2], acc[mi][nj][3],
                            af[mi][0], af[mi][1], af[mi][2], af[mi][3],
                            bf[nj * 2], bf[nj * 2 + 1]);
        }
    }

    __half* op = g_parth + (size_t)(sp * BHn + bh) * (HDd * HDd);
    #pragma unroll
    for (int mi = 0; mi < 6; mi++) {
        const int d = mi * 16 + (lane >> 2);
        #pragma unroll
        for (int nj = 0; nj < 2; nj++) {
            const int e = e0 + nj * 8 + (lane & 3) * 2;
            __half2 v0 = { __float2half_rn(acc[mi][nj][0]), __float2half_rn(acc[mi][nj][1]) };
            __half2 v1 = { __float2half_rn(acc[mi][nj][2]), __float2half_rn(acc[mi][nj][3]) };
            *reinterpret_cast<__half2*>(op + d * HDd + e) = v0;
            *reinterpret_cast<__half2*>(op + (d + 8) * HDd + e) = v1;
        }
    }
}

// ============================================================
// softmax -> fp16 attn (fp16 partials in; no max pass)
// ============================================================
__global__ __launch_bounds__(96) void softmax2_kernel()
{
    const int bh = blockIdx.x;
    const int d  = blockIdx.y;
    const int e  = threadIdx.x;
    const int w  = e >> 5, lane = e & 31;

    __shared__ float s_s[3];

    float sp = 0.f;
    #pragma unroll
    for (int p = 0; p < SPLIT; p++)
        sp += __half2float(g_parth[(size_t)(p * BHn + bh) * (HDd * HDd) + d * HDd + e]);

    const float a = sp * SCALE_F * g_inq[bh * HDd + d] * g_ink[bh * HDd + e];

    const float ex = __expf(a);
    float s = ex;
    #pragma unroll
    for (int o = 16; o > 0; o >>= 1) s += __shfl_xor_sync(0xffffffffu, s, o);
    if (lane == 0) s_s[w] = s;
    __syncthreads();
    s = s_s[0] + s_s[1] + s_s[2];

    g_attnh[(size_t)bh * (HDd * HDd) + d * HDd + e] = __float2half_rn(ex / s);
}

// ============================================================
// mbuild: M^T[b][j][h*96+e] = sum_d attn[b,h,d,e] * Wp[h*96+d, j]
// ============================================================
__global__ __launch_bounds__(128) void mbuild()
{
    __shared__ __half ws[128][GPITCH];   // wpf tile [j][d]
    __shared__ __half as_[96][GPITCH];   // attn [d][e]

    const int jt = blockIdx.x;
    const int bh = blockIdx.y;
    const int b  = bh >> 3;
    const int h  = bh & 7;
    const int j0 = jt * 128;

    const int tid  = threadIdx.x;
    const int lane = tid & 31;
    const int w    = tid >> 5;

    const __half* wsrc = g_wpf + (size_t)j0 * CDIM + h * HDd;
    const __half* asrc = g_attnh + (size_t)bh * (HDd * HDd);
    #pragma unroll
    for (int i = 0; i < 12; i++) {
        const int c = tid + i * 128;
        const int r = c / 12, x = c % 12;
        cp16(s2u(&ws[r][x * 8]), wsrc + (size_t)r * CDIM + x * 8);
    }
    #pragma unroll
    for (int i = 0; i < 9; i++) {
        const int c = tid + i * 128;
        const int r = c / 12, x = c % 12;
        cp16(s2u(&as_[r][x * 8]), asrc + r * HDd + x * 8);
    }
    cp_commit();
    cp_wait<0>();
    __syncthreads();

    const uint32_t aj_row = w * 32 + (lane & 15);
    const uint32_t aj_coff = (lane >> 4) * 8;
    const uint32_t b_row = (lane & 7) + ((lane >> 3) & 1) * 8;
    const uint32_t b_coff = ((lane >> 4) & 1) * 8;

    float acc[2][12][4];
    #pragma unroll
    for (int i = 0; i < 2; i++)
        #pragma unroll
        for (int j = 0; j < 12; j++)
            #pragma unroll
            for (int c = 0; c < 4; c++) acc[i][j][c] = 0.f;

    #pragma unroll
    for (int kc = 0; kc < 6; kc++) {
        uint32_t af[2][4];
        #pragma unroll
        for (int mi = 0; mi < 2; mi++)
            ldsm4(af[mi][0], af[mi][1], af[mi][2], af[mi][3],
                  s2u(&ws[aj_row + mi * 16][kc * 16 + aj_coff]));
        uint32_t bf[12][2];
        #pragma unroll
        for (int p = 0; p < 6; p++) {
            uint32_t r0, r1, r2, r3;
            ldsm4t(r0, r1, r2, r3, s2u(&as_[kc * 16 + b_row][p * 16 + b_coff]));
            bf[2*p][0] = r0; bf[2*p][1] = r1;
            bf[2*p+1][0] = r2; bf[2*p+1][1] = r3;
        }
        #pragma unroll
        for (int mi = 0; mi < 2; mi++)
            #pragma unroll
            for (int nj = 0; nj < 12; nj++)
                mma_f16(acc[mi][nj][0], acc[mi][nj][1], acc[mi][nj][2], acc[mi][nj][3],
                        af[mi][0], af[mi][1], af[mi][2], af[mi][3],
                        bf[nj][0], bf[nj][1]);
    }

    __half* mt = g_mt + (size_t)b * CDIM * CDIM;
    #pragma unroll
    for (int mi = 0; mi < 2; mi++) {
        const int j = j0 + w * 32 + mi * 16 + (lane >> 2);
        #pragma unroll
        for (int nj = 0; nj < 12; nj++) {
            const int e = nj * 8 + (lane & 3) * 2;
            __half2 v0 = { __float2half_rn(acc[mi][nj][0]), __float2half_rn(acc[mi][nj][1]) };
            __half2 v1 = { __float2half_rn(acc[mi][nj][2]), __float2half_rn(acc[mi][nj][3]) };
            *reinterpret_cast<__half2*>(mt + (size_t)j * CDIM + h * HDd + e) = v0;
            *reinterpret_cast<__half2*>(mt + (size_t)(j + 8) * CDIM + h * HDd + e) = v1;
        }
    }
}

// ============================================================
extern "C" void kernel_launch(void* const* d_in, const int* in_sizes, int n_in,
                              void* d_out, int out_size)
{
    const float* cx  = (const float*)d_in[0];
    const float* dx  = (const float*)d_in[1];
    const float* Wq  = (const float*)d_in[2];
    const float* Wkv = (const float*)d_in[3];
    const float* Wp  = (const float*)d_in[4];
    const float* bp  = (const float*)d_in[5];
    float* out = (float*)d_out;

    cudaFuncSetAttribute(gemm_proj, cudaFuncAttributeMaxDynamicSharedMemorySize, GSMEM);
    cudaFuncSetAttribute(gemm_out,  cudaFuncAttributeMaxDynamicSharedMemorySize, GSMEM);

    __half *a1f, *a2f, *wqf, *wkf, *wpf, *qh, *kvh;
    cudaGetSymbolAddress((void**)&a1f, g_a1f);
    cudaGetSymbolAddress((void**)&a2f, g_a2f);
    cudaGetSymbolAddress((void**)&wqf, g_wqf);
    cudaGetSymbolAddress((void**)&wkf, g_wkf);
    cudaGetSymbolAddress((void**)&wpf, g_wpf);
    cudaGetSymbolAddress((void**)&qh,  g_qh);
    cudaGetSymbolAddress((void**)&kvh, g_kvh);

    // all prep in one launch
    prep_all<<<2 * NBC + 2304, 256>>>(cx, a1f, dx, a2f, Wq, Wkv, Wp, wqf, wkf, wpf);

    // q and kv projections + sumsq partials
    gemm_proj<<<dim3(18, MROWS / 128), 256, GSMEM>>>(a1f, wqf, qh, a2f, wkf, kvh);

    // attention core
    norm_reduce<<<BHn, 96>>>();
    gram_tc<<<dim3(BHn, SPLIT), 192>>>();
    softmax2_kernel<<<dim3(BHn, HDd), 96>>>();
    mbuild<<<dim3(6, BHn), 128>>>();

    // out = V @ M_b + bias (av folded into weights)
    gemm_out<<<dim3(CDIM / 128, MROWS / 128), 256, GSMEM>>>(bp, out);
}

// round 17
// speedup vs baseline: 1.4678x; 1.4678x over previous
#include <cuda_runtime.h>
#include <cuda_fp16.h>
#include <cstdint>
#include <cstddef>

// ---------------- problem constants ----------------
#define Bq    4
#define NTOK  4096
#define CDIM  768
#define Hh    8
#define HDd   96
#define MROWS (Bq * NTOK)          // 16384
#define SPLIT 16
#define BHn   (Bq * Hh)            // 32
#define MT    (MROWS / 128)        // 128 m-tiles
#define SCALE_F 0.10206207261596577f
#define EPSN 1e-12f

// ---------------- scratch (device globals) ----------------
__device__ __half g_a1f[(size_t)MROWS * CDIM];       // fp16 context_x
__device__ __half g_a2f[(size_t)MROWS * CDIM];       // fp16 depth_x
__device__ __half g_qh [(size_t)MROWS * CDIM];       // fp16 q
__device__ __half g_kvh[(size_t)MROWS * 2 * CDIM];   // fp16 kv
__device__ __half g_wqf[CDIM * CDIM];
__device__ __half g_wkf[2 * CDIM * CDIM];
__device__ __half g_wpf[CDIM * CDIM];
__device__ __half g_attnh[BHn * HDd * HDd];          // fp16 softmaxed attn
__device__ __half g_mt  [Bq * CDIM * CDIM];          // per-batch folded weights M^T
__device__ float g_part[SPLIT * BHn * HDd * HDd];
__device__ float g_qsqp[MT * CDIM];                  // per-mtile col sumsq (q)
__device__ float g_ksqp[MT * CDIM];                  // per-mtile col sumsq (k)
__device__ float g_inq [BHn * HDd];
__device__ float g_ink [BHn * HDd];

// ---------------- helpers ----------------
__device__ __forceinline__ uint32_t s2u(const void* p) {
    uint32_t a;
    asm("{ .reg .u64 t; cvta.to.shared.u64 t, %1; cvt.u32.u64 %0, t; }" : "=r"(a) : "l"(p));
    return a;
}
__device__ __forceinline__ void cp16(uint32_t dst, const void* src) {
    asm volatile("cp.async.cg.shared.global [%0], [%1], 16;" :: "r"(dst), "l"(src));
}
__device__ __forceinline__ void cp_commit() { asm volatile("cp.async.commit_group;"); }
template <int N>
__device__ __forceinline__ void cp_wait() { asm volatile("cp.async.wait_group %0;" :: "n"(N)); }

__device__ __forceinline__ void ldsm4(uint32_t& r0, uint32_t& r1, uint32_t& r2, uint32_t& r3,
                                      uint32_t addr) {
    asm volatile("ldmatrix.sync.aligned.m8n8.x4.shared.b16 {%0,%1,%2,%3}, [%4];"
                 : "=r"(r0), "=r"(r1), "=r"(r2), "=r"(r3) : "r"(addr));
}
__device__ __forceinline__ void ldsm4t(uint32_t& r0, uint32_t& r1, uint32_t& r2, uint32_t& r3,
                                       uint32_t addr) {
    asm volatile("ldmatrix.sync.aligned.m8n8.x4.trans.shared.b16 {%0,%1,%2,%3}, [%4];"
                 : "=r"(r0), "=r"(r1), "=r"(r2), "=r"(r3) : "r"(addr));
}
__device__ __forceinline__ void mma_f16(float& c0, float& c1, float& c2, float& c3,
                                        uint32_t a0, uint32_t a1, uint32_t a2, uint32_t a3,
                                        uint32_t b0, uint32_t b1) {
    asm volatile(
        "mma.sync.aligned.m16n8k16.row.col.f32.f16.f16.f32 "
        "{%0,%1,%2,%3}, {%4,%5,%6,%7}, {%8,%9}, {%0,%1,%2,%3};"
        : "+f"(c0), "+f"(c1), "+f"(c2), "+f"(c3)
        : "r"(a0), "r"(a1), "r"(a2), "r"(a3), "r"(b0), "r"(b1));
}

// ============================================================
// GEMM core config
// ============================================================
#define PIPE      3
#define TILE_B    16384
#define STAGE_B   (2 * TILE_B)
#define GSMEM     (PIPE * STAGE_B)     // 98304
#define NKT       12
#define NT1       6

// ============================================================
// Fused projection GEMM + column sumsq partials
// ============================================================
__global__ __launch_bounds__(256, 2) void gemm_proj(
    const __half* __restrict__ A1, const __half* __restrict__ B1, __half* __restrict__ O1,
    const __half* __restrict__ A2, const __half* __restrict__ B2, __half* __restrict__ O2)
{
    extern __shared__ __align__(1024) char smem[];
    const uint32_t sbase = s2u(smem);

    const bool j2 = blockIdx.x >= NT1;
    const __half* __restrict__ A = j2 ? A2 : A1;
    const __half* __restrict__ B = j2 ? B2 : B1;
    __half* __restrict__ O = j2 ? O2 : O1;
    const int Nc = j2 ? 2 * CDIM : CDIM;
    const int n0 = (j2 ? (int)blockIdx.x - NT1 : (int)blockIdx.x) * 128;
    const int m0 = blockIdx.y * 128;

    const int tid  = threadIdx.x;
    const int lane = tid & 31;
    const int wid  = tid >> 5;
    const int wm = (wid >> 2) * 64;
    const int wn = (wid & 3) * 32;

    const uint32_t a_row   = wm + (lane & 15);
    const uint32_t a_swz   = (lane & 7) * 16;
    const uint32_t a_xhalf = (lane >> 4) * 16;
    const int l8 = lane & 7;
    const int lg = lane >> 3;
    const uint32_t b_row_base = wn + (lg >> 1) * 8 + l8;
    const uint32_t b_khalf    = (lg & 1) * 16;
    const uint32_t b_swz      = l8 * 16;

    float acc[4][4][4];
    #pragma unroll
    for (int i = 0; i < 4; i++)
        #pragma unroll
        for (int j = 0; j < 4; j++)
            #pragma unroll
            for (int c = 0; c < 4; c++) acc[i][j][c] = 0.f;

    auto issue = [&](int kt, int slot) {
        const int k0 = kt * 64;
        const uint32_t sA = sbase + slot * STAGE_B;
        const uint32_t sB = sA + TILE_B;
        #pragma unroll
        for (int i = 0; i < 8; i++) {
            const int c = tid + i * 256;
            const int row = (c >> 3) & 127;
            const int x16 = c & 7;
            const uint32_t off = (uint32_t)(row * 128 + ((x16 * 16) ^ ((row & 7) * 16)));
            if (c < 1024) cp16(sA + off, A + (size_t)(m0 + row) * CDIM + k0 + x16 * 8);
            else          cp16(sB + off, B + (size_t)(n0 + row) * CDIM + k0 + x16 * 8);
        }
        cp_commit();
    };

    issue(0, 0); issue(1, 1);

    for (int kt = 0; kt < NKT; kt++) {
        const int slot = kt % 3;
        cp_wait<PIPE - 2>();
        __syncthreads();
        if (kt + 2 < NKT) issue(kt + 2, (kt + 2) % 3);

        const uint32_t sA = sbase + slot * STAGE_B;
        const uint32_t sB = sA + TILE_B;

        #pragma unroll
        for (int ks = 0; ks < 4; ks++) {
            uint32_t af[4][4];
            #pragma unroll
            for (int mi = 0; mi < 4; mi++) {
                const uint32_t addr = sA + (a_row + mi * 16) * 128
                                    + ((ks * 32 + a_xhalf) ^ a_swz);
                ldsm4(af[mi][0], af[mi][1], af[mi][2], af[mi][3], addr);
            }
            uint32_t bf[4][2];
            #pragma unroll
            for (int p = 0; p < 2; p++) {
                const uint32_t addr = sB + (b_row_base + p * 16) * 128
                                    + ((ks * 32 + b_khalf) ^ b_swz);
                ldsm4(bf[2*p][0], bf[2*p][1], bf[2*p+1][0], bf[2*p+1][1], addr);
            }
            #pragma unroll
            for (int mi = 0; mi < 4; mi++)
                #pragma unroll
                for (int nj = 0; nj < 4; nj++)
                    mma_f16(acc[mi][nj][0], acc[mi][nj][1], acc[mi][nj][2], acc[mi][nj][3],
                            af[mi][0], af[mi][1], af[mi][2], af[mi][3],
                            bf[nj][0], bf[nj][1]);
        }
    }

    #pragma unroll
    for (int mi = 0; mi < 4; mi++) {
        const int r0 = m0 + wm + mi * 16 + (lane >> 2);
        #pragma unroll
        for (int nj = 0; nj < 4; nj++) {
            const int c = n0 + wn + nj * 8 + (lane & 3) * 2;
            __half2 v0 = { __float2half_rn(acc[mi][nj][0]), __float2half_rn(acc[mi][nj][1]) };
            __half2 v1 = { __float2half_rn(acc[mi][nj][2]), __float2half_rn(acc[mi][nj][3]) };
            *reinterpret_cast<__half2*>(O + (size_t)r0 * Nc + c) = v0;
            *reinterpret_cast<__half2*>(O + (size_t)(r0 + 8) * Nc + c) = v1;
        }
    }

    // ---- fused column sum-of-squares ----
    const bool need_sq = (!j2) || (n0 < CDIM);
    if (need_sq) {
        float* colsq = reinterpret_cast<float*>(smem);   // [2][128]
        __syncthreads();
        #pragma unroll
        for (int nj = 0; nj < 4; nj++) {
            float s0 = 0.f, s1 = 0.f;
            #pragma unroll
            for (int mi = 0; mi < 4; mi++) {
                s0 += acc[mi][nj][0] * acc[mi][nj][0] + acc[mi][nj][2] * acc[mi][nj][2];
                s1 += acc[mi][nj][1] * acc[mi][nj][1] + acc[mi][nj][3] * acc[mi][nj][3];
            }
            #pragma unroll
            for (int o = 4; o < 32; o <<= 1) {
                s0 += __shfl_xor_sync(0xffffffffu, s0, o);
                s1 += __shfl_xor_sync(0xffffffffu, s1, o);
            }
            if (lane < 4) {
                const int col = wn + nj * 8 + lane * 2;
                colsq[(wm >> 6) * 128 + col]     = s0;
                colsq[(wm >> 6) * 128 + col + 1] = s1;
            }
        }
        __syncthreads();
        if (tid < 128) {
            const float tot = colsq[tid] + colsq[128 + tid];
            float* dst = j2 ? g_ksqp : g_qsqp;
            dst[(size_t)blockIdx.y * CDIM + n0 + tid] = tot;
        }
    }
}

// ============================================================
// Final GEMM: out = V @ M_b + bias, fp32 output
// ============================================================
__global__ __launch_bounds__(256, 2) void gemm_out(
    const float* __restrict__ bias, float* __restrict__ Cout)
{
    extern __shared__ __align__(1024) char smem[];
    const uint32_t sbase = s2u(smem);
    const int Nc = CDIM;

    const int tid  = threadIdx.x;
    const int lane = tid & 31;
    const int wid  = tid >> 5;
    const int m0 = blockIdx.y * 128;
    const int n0 = blockIdx.x * 128;
    const int wm = (wid >> 2) * 64;
    const int wn = (wid & 3) * 32;

    const __half* __restrict__ A = g_kvh + CDIM;          // v half, row stride 2C
    const __half* __restrict__ B = g_mt + (size_t)(blockIdx.y >> 5) * CDIM * CDIM;

    const uint32_t a_row   = wm + (lane & 15);
    const uint32_t a_swz   = (lane & 7) * 16;
    const uint32_t a_xhalf = (lane >> 4) * 16;
    const int l8 = lane & 7;
    const int lg = lane >> 3;
    const uint32_t b_row_base = wn + (lg >> 1) * 8 + l8;
    const uint32_t b_khalf    = (lg & 1) * 16;
    const uint32_t b_swz      = l8 * 16;

    float acc[4][4][4];
    #pragma unroll
    for (int i = 0; i < 4; i++)
        #pragma unroll
        for (int j = 0; j < 4; j++)
            #pragma unroll
            for (int c = 0; c < 4; c++) acc[i][j][c] = 0.f;

    auto issue = [&](int kt, int slot) {
        const int k0 = kt * 64;
        const uint32_t sA = sbase + slot * STAGE_B;
        const uint32_t sB = sA + TILE_B;
        #pragma unroll
        for (int i = 0; i < 8; i++) {
            const int c = tid + i * 256;
            const int row = (c >> 3) & 127;
            const int x16 = c & 7;
            const uint32_t off = (uint32_t)(row * 128 + ((x16 * 16) ^ ((row & 7) * 16)));
            if (c < 1024) cp16(sA + off, A + (size_t)(m0 + row) * (2 * CDIM) + k0 + x16 * 8);
            else          cp16(sB + off, B + (size_t)(n0 + row) * CDIM + k0 + x16 * 8);
        }
        cp_commit();
    };

    issue(0, 0); issue(1, 1);

    for (int kt = 0; kt < NKT; kt++) {
        const int slot = kt % 3;
        cp_wait<PIPE - 2>();
        __syncthreads();
        if (kt + 2 < NKT) issue(kt + 2, (kt + 2) % 3);

        const uint32_t sA = sbase + slot * STAGE_B;
        const uint32_t sB = sA + TILE_B;

        #pragma unroll
        for (int ks = 0; ks < 4; ks++) {
            uint32_t af[4][4];
            #pragma unroll
            for (int mi = 0; mi < 4; mi++) {
                const uint32_t addr = sA + (a_row + mi * 16) * 128
                                    + ((ks * 32 + a_xhalf) ^ a_swz);
                ldsm4(af[mi][0], af[mi][1], af[mi][2], af[mi][3], addr);
            }
            uint32_t bf[4][2];
            #pragma unroll
            for (int p = 0; p < 2; p++) {
                const uint32_t addr = sB + (b_row_base + p * 16) * 128
                                    + ((ks * 32 + b_khalf) ^ b_swz);
                ldsm4(bf[2*p][0], bf[2*p][1], bf[2*p+1][0], bf[2*p+1][1], addr);
            }
            #pragma unroll
            for (int mi = 0; mi < 4; mi++)
                #pragma unroll
                for (int nj = 0; nj < 4; nj++)
                    mma_f16(acc[mi][nj][0], acc[mi][nj][1], acc[mi][nj][2], acc[mi][nj][3],
                            af[mi][0], af[mi][1], af[mi][2], af[mi][3],
                            bf[nj][0], bf[nj][1]);
        }
    }

    #pragma unroll
    for (int mi = 0; mi < 4; mi++) {
        const int r0 = m0 + wm + mi * 16 + (lane >> 2);
        #pragma unroll
        for (int nj = 0; nj < 4; nj++) {
            const int c = n0 + wn + nj * 8 + (lane & 3) * 2;
            const float b0 = bias[c], b1 = bias[c + 1];
            float2 v0 = { acc[mi][nj][0] + b0, acc[mi][nj][1] + b1 };
            float2 v1 = { acc[mi][nj][2] + b0, acc[mi][nj][3] + b1 };
            *reinterpret_cast<float2*>(Cout + (size_t)r0 * Nc + c) = v0;
            *reinterpret_cast<float2*>(Cout + (size_t)(r0 + 8) * Nc + c) = v1;
        }
    }
}

// ============================================================
// Fused prep: fp32->fp16 converts + weight transposes
// ============================================================
#define NBC 12288

__global__ __launch_bounds__(256) void prep_all(
    const float* __restrict__ cx, __half* __restrict__ a1f,
    const float* __restrict__ dx, __half* __restrict__ a2f,
    const float* __restrict__ Wq, const float* __restrict__ Wkv,
    const float* __restrict__ Wp,
    __half* __restrict__ Tq, __half* __restrict__ Tk, __half* __restrict__ Tp)
{
    const int bx = blockIdx.x;
    if (bx < 2 * NBC) {
        const bool sec = bx >= NBC;
        const float* in = sec ? dx : cx;
        __half* out = sec ? a2f : a1f;
        const int i = (sec ? bx - NBC : bx) * 256 + threadIdx.x;
        const float4 v = reinterpret_cast<const float4*>(in)[i];
        __half2 h0 = { __float2half_rn(v.x), __float2half_rn(v.y) };
        __half2 h1 = { __float2half_rn(v.z), __float2half_rn(v.w) };
        reinterpret_cast<__half2*>(out)[i * 2 + 0] = h0;
        reinterpret_cast<__half2*>(out)[i * 2 + 1] = h1;
        return;
    }
    __shared__ float t[32][33];
    const int w = bx - 2 * NBC;
    const int bnx = w % 96;
    const int k0 = (w / 96) * 32;
    const float* W; __half* T; int Nc, nt0;
    if (bnx < 24)      { W = Wq;  T = Tq; Nc = CDIM;     nt0 = 0; }
    else if (bnx < 72) { W = Wkv; T = Tk; Nc = 2 * CDIM; nt0 = 24; }
    else               { W = Wp;  T = Tp; Nc = CDIM;     nt0 = 72; }
    const int n0 = (bnx - nt0) * 32;
    const int tx = threadIdx.x & 31, ty = threadIdx.x >> 5;
    #pragma unroll
    for (int i = 0; i < 32; i += 8)
        t[ty + i][tx] = W[(size_t)(k0 + ty + i) * Nc + n0 + tx];
    __syncthreads();
    #pragma unroll
    for (int i = 0; i < 32; i += 8)
        T[(size_t)(n0 + ty + i) * CDIM + k0 + tx] = __float2half_rn(t[tx][ty + i]);
}

// ============================================================
// Reduce per-mtile partials -> reciprocal norms
// ============================================================
__global__ __launch_bounds__(96) void norm_reduce()
{
    const int bh = blockIdx.x;
    const int b  = bh >> 3;
    const int h  = bh & 7;
    const int d  = threadIdx.x;
    const int col = h * HDd + d;
    float sq = 0.f, sk = 0.f;
    #pragma unroll 8
    for (int j = 0; j < 32; j++) {
        sq += g_qsqp[(size_t)(b * 32 + j) * CDIM + col];
        sk += g_ksqp[(size_t)(b * 32 + j) * CDIM + col];
    }
    g_inq[bh * HDd + d] = 1.f / fmaxf(sqrtf(sq), EPSN);
    g_ink[bh * HDd + d] = 1.f / fmaxf(sqrtf(sk), EPSN);
}

// ============================================================
// Tensor-core Gram partials: 32-token stages, 3-stage pipe
// grid (BHn, SPLIT=16); 256 tokens per block; GNI=8
// ============================================================
#define GPITCH 104
#define GNI    8
#define GSTG   3

__global__ __launch_bounds__(192) void gram_tc()
{
    __shared__ __half qs[GSTG][32][GPITCH];
    __shared__ __half ks[GSTG][32][GPITCH];

    const int bh = blockIdx.x;
    const int b  = bh >> 3;
    const int h  = bh & 7;
    const int sp = blockIdx.y;
    const int nbase = b * NTOK + sp * (NTOK / SPLIT);

    const int tid  = threadIdx.x;
    const int lane = tid & 31;
    const int w    = tid >> 5;
    const int e0   = w * 16;

    const __half* qbase = g_qh  + (size_t)nbase * CDIM + h * HDd;
    const __half* kbase = g_kvh + (size_t)nbase * (2 * CDIM) + h * HDd;

    auto issue = [&](int it, int s) {
        const int n0 = it * 32;
        #pragma unroll
        for (int r = 0; r < 2; r++) {
            const int c = tid + r * 192;
            const int lrow = c / 12;
            const int lx   = c % 12;
            cp16(s2u(&qs[s][lrow][lx * 8]),
                 qbase + (size_t)(n0 + lrow) * CDIM + lx * 8);
            cp16(s2u(&ks[s][lrow][lx * 8]),
                 kbase + (size_t)(n0 + lrow) * (2 * CDIM) + lx * 8);
        }
        cp_commit();
    };

    const uint32_t a_row = (lane & 7) + ((lane >> 4) & 1) * 8;
    const uint32_t a_coff = ((lane >> 3) & 1) * 8;
    const uint32_t b_row = (lane & 7) + ((lane >> 3) & 1) * 8;
    const uint32_t b_coff = ((lane >> 4) & 1) * 8;

    float acc[6][2][4];
    #pragma unroll
    for (int i = 0; i < 6; i++)
        #pragma unroll
        for (int j = 0; j < 2; j++)
            #pragma unroll
            for (int c = 0; c < 4; c++) acc[i][j][c] = 0.f;

    issue(0, 0); issue(1, 1);

    #pragma unroll 1
    for (int it = 0; it < GNI; it++) {
        const int s = it % GSTG;
        if (it + 1 < GNI) cp_wait<1>(); else cp_wait<0>();
        __syncthreads();
        if (it + 2 < GNI) issue(it + 2, (it + 2) % GSTG);

        #pragma unroll
        for (int hs = 0; hs < 2; hs++) {
            uint32_t bf[4];
            ldsm4t(bf[0], bf[1], bf[2], bf[3],
                   s2u(&ks[s][hs * 16 + b_row][e0 + b_coff]));
            uint32_t af[6][4];
            #pragma unroll
            for (int mi = 0; mi < 6; mi++)
                ldsm4t(af[mi][0], af[mi][1], af[mi][2], af[mi][3],
                       s2u(&qs[s][hs * 16 + a_row][mi * 16 + a_coff]));
            #pragma unroll
            for (int mi = 0; mi < 6; mi++)
                #pragma unroll
                for (int nj = 0; nj < 2; nj++)
                    mma_f16(acc[mi][nj][0], acc[mi][nj][1], acc[mi][nj][2], acc[mi][nj][3],
                            af[mi][0], af[mi][1], af[mi][2], af[mi][3],
                            bf[nj * 2], bf[nj * 2 + 1]);
        }
    }

    float* op = g_part + (size_t)(sp * BHn + bh) * (HDd * HDd);
    #pragma unroll
    for (int mi = 0; mi < 6; mi++) {
        const int d = mi * 16 + (lane >> 2);
        #pragma unroll
        for (int nj = 0; nj < 2; nj++) {
            const int e = e0 + nj * 8 + (lane & 3) * 2;
            float2 v0 = { acc[mi][nj][0], acc[mi][nj][1] };
            float2 v1 = { acc[mi][nj][2], acc[mi][nj][3] };
            *reinterpret_cast<float2*>(op + d * HDd + e) = v0;
            *reinterpret_cast<float2*>(op + (d + 8) * HDd + e) = v1;
        }
    }
}

// ============================================================
// softmax -> fp16 attn (no max pass: |logit| <= ~0.103)
// ============================================================
__global__ __launch_bounds__(96) void softmax2_kernel()
{
    const int bh = blockIdx.x;
    const int d  = blockIdx.y;
    const int e  = threadIdx.x;
    const int w  = e >> 5, lane = e & 31;

    __shared__ float s_s[3];

    float sp = 0.f;
    #pragma unroll
    for (int p = 0; p < SPLIT; p++)
        sp += g_part[(size_t)(p * BHn + bh) * (HDd * HDd) + d * HDd + e];

    const float a = sp * SCALE_F * g_inq[bh * HDd + d] * g_ink[bh * HDd + e];

    const float ex = __expf(a);
    float s = ex;
    #pragma unroll
    for (int o = 16; o > 0; o >>= 1) s += __shfl_xor_sync(0xffffffffu, s, o);
    if (lane == 0) s_s[w] = s;
    __syncthreads();
    s = s_s[0] + s_s[1] + s_s[2];

    g_attnh[(size_t)bh * (HDd * HDd) + d * HDd + e] = __float2half_rn(ex / s);
}

// ============================================================
// mbuild: M^T[b][j][h*96+e] = sum_d attn[b,h,d,e] * Wp[h*96+d, j]
// ============================================================
__global__ __launch_bounds__(128) void mbuild()
{
    __shared__ __half ws[128][GPITCH];   // wpf tile [j][d]
    __shared__ __half as_[96][GPITCH];   // attn [d][e]

    const int jt = blockIdx.x;
    const int bh = blockIdx.y;
    const int b  = bh >> 3;
    const int h  = bh & 7;
    const int j0 = jt * 128;

    const int tid  = threadIdx.x;
    const int lane = tid & 31;
    const int w    = tid >> 5;

    const __half* wsrc = g_wpf + (size_t)j0 * CDIM + h * HDd;
    const __half* asrc = g_attnh + (size_t)bh * (HDd * HDd);
    #pragma unroll
    for (int i = 0; i < 12; i++) {
        const int c = tid + i * 128;
        const int r = c / 12, x = c % 12;
        cp16(s2u(&ws[r][x * 8]), wsrc + (size_t)r * CDIM + x * 8);
    }
    #pragma unroll
    for (int i = 0; i < 9; i++) {
        const int c = tid + i * 128;
        const int r = c / 12, x = c % 12;
        cp16(s2u(&as_[r][x * 8]), asrc + r * HDd + x * 8);
    }
    cp_commit();
    cp_wait<0>();
    __syncthreads();

    const uint32_t aj_row = w * 32 + (lane & 15);
    const uint32_t aj_coff = (lane >> 4) * 8;
    const uint32_t b_row = (lane & 7) + ((lane >> 3) & 1) * 8;
    const uint32_t b_coff = ((lane >> 4) & 1) * 8;

    float acc[2][12][4];
    #pragma unroll
    for (int i = 0; i < 2; i++)
        #pragma unroll
        for (int j = 0; j < 12; j++)
            #pragma unroll
            for (int c = 0; c < 4; c++) acc[i][j][c] = 0.f;

    #pragma unroll
    for (int kc = 0; kc < 6; kc++) {
        uint32_t af[2][4];
        #pragma unroll
        for (int mi = 0; mi < 2; mi++)
            ldsm4(af[mi][0], af[mi][1], af[mi][2], af[mi][3],
                  s2u(&ws[aj_row + mi * 16][kc * 16 + aj_coff]));
        uint32_t bf[12][2];
        #pragma unroll
        for (int p = 0; p < 6; p++) {
            uint32_t r0, r1, r2, r3;
            ldsm4t(r0, r1, r2, r3, s2u(&as_[kc * 16 + b_row][p * 16 + b_coff]));
            bf[2*p][0] = r0; bf[2*p][1] = r1;
            bf[2*p+1][0] = r2; bf[2*p+1][1] = r3;
        }
        #pragma unroll
        for (int mi = 0; mi < 2; mi++)
            #pragma unroll
            for (int nj = 0; nj < 12; nj++)
                mma_f16(acc[mi][nj][0], acc[mi][nj][1], acc[mi][nj][2], acc[mi][nj][3],
                        af[mi][0], af[mi][1], af[mi][2], af[mi][3],
                        bf[nj][0], bf[nj][1]);
    }

    __half* mt = g_mt + (size_t)b * CDIM * CDIM;
    #pragma unroll
    for (int mi = 0; mi < 2; mi++) {
        const int j = j0 + w * 32 + mi * 16 + (lane >> 2);
        #pragma unroll
        for (int nj = 0; nj < 12; nj++) {
            const int e = nj * 8 + (lane & 3) * 2;
            __half2 v0 = { __float2half_rn(acc[mi][nj][0]), __float2half_rn(acc[mi][nj][1]) };
            __half2 v1 = { __float2half_rn(acc[mi][nj][2]), __float2half_rn(acc[mi][nj][3]) };
            *reinterpret_cast<__half2*>(mt + (size_t)j * CDIM + h * HDd + e) = v0;
            *reinterpret_cast<__half2*>(mt + (size_t)(j + 8) * CDIM + h * HDd + e) = v1;
        }
    }
}

// ============================================================
extern "C" void kernel_launch(void* const* d_in, const int* in_sizes, int n_in,
                              void* d_out, int out_size)
{
    const float* cx  = (const float*)d_in[0];
    const float* dx  = (const float*)d_in[1];
    const float* Wq  = (const float*)d_in[2];
    const float* Wkv = (const float*)d_in[3];
    const float* Wp  = (const float*)d_in[4];
    const float* bp  = (const float*)d_in[5];
    float* out = (float*)d_out;

    cudaFuncSetAttribute(gemm_proj, cudaFuncAttributeMaxDynamicSharedMemorySize, GSMEM);
    cudaFuncSetAttribute(gemm_out,  cudaFuncAttributeMaxDynamicSharedMemorySize, GSMEM);

    __half *a1f, *a2f, *wqf, *wkf, *wpf, *qh, *kvh;
    cudaGetSymbolAddress((void**)&a1f, g_a1f);
    cudaGetSymbolAddress((void**)&a2f, g_a2f);
    cudaGetSymbolAddress((void**)&wqf, g_wqf);
    cudaGetSymbolAddress((void**)&wkf, g_wkf);
    cudaGetSymbolAddress((void**)&wpf, g_wpf);
    cudaGetSymbolAddress((void**)&qh,  g_qh);
    cudaGetSymbolAddress((void**)&kvh, g_kvh);

    // all prep in one launch
    prep_all<<<2 * NBC + 2304, 256>>>(cx, a1f, dx, a2f, Wq, Wkv, Wp, wqf, wkf, wpf);

    // q and kv projections + sumsq partials
    gemm_proj<<<dim3(18, MROWS / 128), 256, GSMEM>>>(a1f, wqf, qh, a2f, wkf, kvh);

    // attention core
    norm_reduce<<<BHn, 96>>>();
    gram_tc<<<dim3(BHn, SPLIT), 192>>>();
    softmax2_kernel<<<dim3(BHn, HDd), 96>>>();
    mbuild<<<dim3(6, BHn), 128>>>();

    // out = V @ M_b + bias (av folded into weights)
    gemm_out<<<dim3(CDIM / 128, MROWS / 128), 256, GSMEM>>>(bp, out);
}